// round 2
// baseline (speedup 1.0000x reference)
#include <cuda_runtime.h>
#include <cstdint>

#define NTHREADS 256
#define ROWLEN   4096
#define KSEL     8
#define RPB      4          // rows per block (software-pipelined)
#define POOL_CAP 128

typedef unsigned long long u64;

// Monotone bijection float -> uint32 (order preserving, no NaNs in data)
__device__ __forceinline__ unsigned fflip(float f) {
    unsigned u = __float_as_uint(f);
    return (u & 0x80000000u) ? ~u : (u | 0x80000000u);
}
__device__ __forceinline__ float funflip(unsigned u) {
    return __uint_as_float((u & 0x80000000u) ? (u ^ 0x80000000u) : ~u);
}

struct Shared {
    unsigned wthr[8];     // per-warp 8th-largest group-max (flipped)
    int      cnt;
    u64      pool[POOL_CAP];
};

__device__ __forceinline__ void load_row(const float* __restrict__ in,
                                         size_t row, int t, float4 v[4]) {
    const float4* rp = reinterpret_cast<const float4*>(in + row * (size_t)ROWLEN);
    v[0] = __ldcs(rp + t);
    v[1] = __ldcs(rp + 256 + t);
    v[2] = __ldcs(rp + 512 + t);
    v[3] = __ldcs(rp + 768 + t);
}

__device__ __forceinline__ void process_row(const float4 v[4], size_t row,
                                            float* __restrict__ out,
                                            Shared* s, int t) {
    const int lane = t & 31;
    const int wid  = t >> 5;

    // --- per-thread group max over its 16 elements ---
    float m01 = fmaxf(fmaxf(fmaxf(v[0].x, v[0].y), fmaxf(v[0].z, v[0].w)),
                      fmaxf(fmaxf(v[1].x, v[1].y), fmaxf(v[1].z, v[1].w)));
    float m23 = fmaxf(fmaxf(fmaxf(v[2].x, v[2].y), fmaxf(v[2].z, v[2].w)),
                      fmaxf(fmaxf(v[3].x, v[3].y), fmaxf(v[3].z, v[3].w)));
    float gmax = fmaxf(m01, m23);

    // --- bitonic sort of 32 group-maxes across the warp (ascending), no smem ---
    unsigned gx = fflip(gmax);
#pragma unroll
    for (int k = 2; k <= 32; k <<= 1) {
#pragma unroll
        for (int j = k >> 1; j > 0; j >>= 1) {
            unsigned o = __shfl_xor_sync(0xffffffffu, gx, j);
            bool take_max = (((lane & j) != 0) ^ ((lane & k) != 0));
            gx = take_max ? max(gx, o) : min(gx, o);
        }
    }
    // 8th largest of this warp's 32 group maxes sits at lane 24
    unsigned wthr = __shfl_sync(0xffffffffu, gx, 24);
    if (lane == 0) s->wthr[wid] = wthr;
    if (t == 0)    s->cnt = 0;
    __syncthreads();

    // block threshold: MAX over warps (tighter filter, still safe: the winning
    // warp's top-8 group maxes are >= T, so >=8 elements >= T exist; any true
    // top-8 element x must satisfy x >= T).
    unsigned tf = s->wthr[0];
#pragma unroll
    for (int i = 1; i < 8; i++) tf = max(tf, s->wthr[i]);
    const float thr = funflip(tf);

    // --- push candidate ELEMENTS (x >= thr) into tiny pool ---
    if (gmax >= thr) {
#pragma unroll
        for (int c = 0; c < 4; c++) {
            const float* e = reinterpret_cast<const float*>(&v[c]);
#pragma unroll
            for (int j = 0; j < 4; j++) {
                float x = e[j];
                if (x >= thr) {
                    int pos = atomicAdd(&s->cnt, 1);
                    if (pos < POOL_CAP) {
                        int idx = c * 1024 + 4 * t + j;
                        s->pool[pos] = ((u64)fflip(x) << 12) | (unsigned)(4095 - idx);
                    }
                }
            }
        }
    }
    __syncthreads();

    // --- warp 0: select top-8 keys (value desc, index asc), write in index order ---
    if (t < 32) {
        const int n = min(s->cnt, POOL_CAP);
        u64 mykey = 0ull;
#pragma unroll 1
        for (int k = 0; k < KSEL; k++) {
            u64 best = 0ull; int bpos = -1;
            for (int p = t; p < n; p += 32) {
                u64 key = s->pool[p];
                if (key > best) { best = key; bpos = p; }
            }
#pragma unroll
            for (int off = 16; off > 0; off >>= 1) {
                u64 ob = __shfl_xor_sync(0xffffffffu, best, off);
                int op = __shfl_xor_sync(0xffffffffu, bpos, off);
                if (ob > best) { best = ob; bpos = op; }
            }
            if (t == k) mykey = best;
            if (t == 0) s->pool[bpos] = 0ull;   // keys are unique & nonzero
            __syncwarp();
        }
        if (t < KSEL) {
            unsigned fb = (unsigned)(mykey >> 12);
            float val = funflip(fb);
            int idx = 4095 - (int)(mykey & 0xfffu);
            int rank = 0;
#pragma unroll
            for (int j = 0; j < KSEL; j++) {
                int oi = __shfl_sync(0xffu, idx, j);
                rank += (oi < idx);
            }
            out[row * KSEL + rank] = val;
        }
    }
}

__global__ __launch_bounds__(NTHREADS) void kmax_kernel(const float* __restrict__ in,
                                                        float* __restrict__ out,
                                                        int rows) {
    __shared__ Shared s;
    const int t = threadIdx.x;
    const size_t base = (size_t)blockIdx.x * RPB;

    float4 bufA[4], bufB[4];
    load_row(in, base, t, bufA);

#pragma unroll
    for (int r = 0; r < RPB; r++) {
        float4* cur = (r & 1) ? bufB : bufA;
        float4* nxt = (r & 1) ? bufA : bufB;
        if (r + 1 < RPB && base + r + 1 < (size_t)rows)
            load_row(in, base + r + 1, t, nxt);      // prefetch before compute/syncs
        if (base + r < (size_t)rows)
            process_row(cur, base + r, out, &s, t);
    }
}

extern "C" void kernel_launch(void* const* d_in, const int* in_sizes, int n_in,
                              void* d_out, int out_size) {
    const float* in = (const float*)d_in[0];
    float* out = (float*)d_out;
    int rows = in_sizes[0] / ROWLEN;                 // B*C = 16384
    int grid = (rows + RPB - 1) / RPB;               // 4096
    kmax_kernel<<<grid, NTHREADS>>>(in, out, rows);
}

// round 3
// speedup vs baseline: 1.7523x; 1.7523x over previous
#include <cuda_runtime.h>
#include <cstdint>

#define NTHREADS 256
#define ROWLEN   4096
#define KSEL     8
#define POOL_CAP 512

typedef unsigned long long u64;

// Monotone bijection float -> uint32 (order preserving)
__device__ __forceinline__ unsigned fflip(float f) {
    unsigned u = __float_as_uint(f);
    return (u & 0x80000000u) ? ~u : (u | 0x80000000u);
}
__device__ __forceinline__ float funflip(unsigned u) {
    return __uint_as_float((u & 0x80000000u) ? (u ^ 0x80000000u) : ~u);
}

__global__ __launch_bounds__(NTHREADS) void kmax_kernel(const float* __restrict__ in,
                                                        float* __restrict__ out) {
    __shared__ unsigned s_wthr[8];
    __shared__ int s_cnt;
    __shared__ u64 s_pool[POOL_CAP];

    const int t = threadIdx.x;
    const int lane = t & 31;
    const int wid = t >> 5;
    const size_t row = blockIdx.x;
    const float4* rp = reinterpret_cast<const float4*>(in + row * (size_t)ROWLEN);

    // Front-batched streaming loads: 4x LDG.128 per thread.
    float4 v0 = __ldcs(rp + t);
    float4 v1 = __ldcs(rp + 256 + t);
    float4 v2 = __ldcs(rp + 512 + t);
    float4 v3 = __ldcs(rp + 768 + t);

    if (t == 0) s_cnt = 0;

    // Per-thread group max over its 16 elements.
    float m01 = fmaxf(fmaxf(fmaxf(v0.x, v0.y), fmaxf(v0.z, v0.w)),
                      fmaxf(fmaxf(v1.x, v1.y), fmaxf(v1.z, v1.w)));
    float m23 = fmaxf(fmaxf(fmaxf(v2.x, v2.y), fmaxf(v2.z, v2.w)),
                      fmaxf(fmaxf(v3.x, v3.y), fmaxf(v3.z, v3.w)));
    const float gmax = fmaxf(m01, m23);

    // Warp-parallel: bitonic sort 32 group-maxes (ascending); 8th largest at lane 24.
    unsigned gx = fflip(gmax);
#pragma unroll
    for (int k = 2; k <= 32; k <<= 1) {
#pragma unroll
        for (int j = k >> 1; j > 0; j >>= 1) {
            unsigned o = __shfl_xor_sync(0xffffffffu, gx, j);
            bool take_max = (((lane & j) != 0) ^ ((lane & k) != 0));
            gx = take_max ? max(gx, o) : min(gx, o);
        }
    }
    unsigned wthr = __shfl_sync(0xffffffffu, gx, 24);
    if (lane == 0) s_wthr[wid] = wthr;
    __syncthreads();

    // Block threshold = MAX over the 8 per-warp values. Safe: the winning warp
    // has 8 group maxes >= T (each is a real element), so >=8 elements >= T;
    // any true top-8 element x must therefore satisfy x >= T.
    unsigned tf = s_wthr[0];
#pragma unroll
    for (int i = 1; i < 8; i++) tf = max(tf, s_wthr[i]);
    const float thr = funflip(tf);

    // Push candidate ELEMENTS (x >= thr). Typically ~8-15 per row.
    if (gmax >= thr) {
        const float4 vv[4] = {v0, v1, v2, v3};
#pragma unroll
        for (int c = 0; c < 4; c++) {
            const float* e = reinterpret_cast<const float*>(&vv[c]);
#pragma unroll
            for (int j = 0; j < 4; j++) {
                float x = e[j];
                if (x >= thr) {
                    int pos = atomicAdd(&s_cnt, 1);
                    if (pos < POOL_CAP) {
                        int idx = c * 1024 + 4 * t + j;
                        s_pool[pos] = ((u64)fflip(x) << 12) | (unsigned)(4095 - idx);
                    }
                }
            }
        }
    }
    __syncthreads();

    // Warp 0: select top-8 keys (key = value desc, index asc), write in index order.
    if (t < 32) {
        const int n = min(s_cnt, POOL_CAP);
        u64 mykey;   // set in both paths below before use

        if (n <= 32) {
            // FAST PATH: one 32-lane bitonic sort of the padded pool.
            u64 key = (t < n) ? s_pool[t] : 0ull;   // keys unique & nonzero
#pragma unroll
            for (int k = 2; k <= 32; k <<= 1) {
#pragma unroll
                for (int j = k >> 1; j > 0; j >>= 1) {
                    u64 o = __shfl_xor_sync(0xffffffffu, key, j);
                    bool take_max = (((lane & j) != 0) ^ (((lane & k) != 0) && k < 32));
                    key = take_max ? (key > o ? key : o) : (key < o ? key : o);
                }
            }
            // ascending sort: top-8 at lanes 24..31
            mykey = key;
            if (t >= 32 - KSEL) {
                unsigned fb = (unsigned)(mykey >> 12);
                float val = funflip(fb);
                int idx = 4095 - (int)(mykey & 0xfffu);
                int rank = 0;
#pragma unroll
                for (int j = 24; j < 32; j++) {
                    int oi = __shfl_sync(0xffffffffu, idx, j);
                    rank += (oi < idx);
                }
                out[row * KSEL + rank] = val;
            }
        } else {
            // SLOW PATH (pathological ties): 8 rounds of warp argmax.
            mykey = 0ull;
#pragma unroll 1
            for (int k = 0; k < KSEL; k++) {
                u64 best = 0ull; int bpos = -1;
                for (int p = t; p < n; p += 32) {
                    u64 key = s_pool[p];
                    if (key > best) { best = key; bpos = p; }
                }
#pragma unroll
                for (int off = 16; off > 0; off >>= 1) {
                    u64 ob = __shfl_xor_sync(0xffffffffu, best, off);
                    int op = __shfl_xor_sync(0xffffffffu, bpos, off);
                    if (ob > best) { best = ob; bpos = op; }
                }
                if (t == k) mykey = best;
                if (t == 0) s_pool[bpos] = 0ull;
                __syncwarp();
            }
            if (t < KSEL) {
                unsigned fb = (unsigned)(mykey >> 12);
                float val = funflip(fb);
                int idx = 4095 - (int)(mykey & 0xfffu);
                int rank = 0;
#pragma unroll
                for (int j = 0; j < KSEL; j++) {
                    int oi = __shfl_sync(0xffu, idx, j);
                    rank += (oi < idx);
                }
                out[row * KSEL + rank] = val;
            }
        }
    }
}

extern "C" void kernel_launch(void* const* d_in, const int* in_sizes, int n_in,
                              void* d_out, int out_size) {
    const float* in = (const float*)d_in[0];
    float* out = (float*)d_out;
    int rows = in_sizes[0] / ROWLEN;   // B*C = 16384
    kmax_kernel<<<rows, NTHREADS>>>(in, out);
}

// round 4
// speedup vs baseline: 2.8164x; 1.6073x over previous
#include <cuda_runtime.h>
#include <cstdint>

#define NTHREADS 256
#define ROWLEN   4096
#define KSEL     8
#define POOL_CAP 256

typedef unsigned long long u64;

// Monotone bijection float -> uint32 (order preserving)
__device__ __forceinline__ unsigned fflip(float f) {
    unsigned u = __float_as_uint(f);
    return (u & 0x80000000u) ? ~u : (u | 0x80000000u);
}
__device__ __forceinline__ float funflip(unsigned u) {
    return __uint_as_float((u & 0x80000000u) ? (u ^ 0x80000000u) : ~u);
}

__global__ __launch_bounds__(NTHREADS) void kmax_kernel(const float* __restrict__ in,
                                                        float* __restrict__ out) {
    __shared__ unsigned s_m[16];      // per-warp {m1, m2} (flipped), 8 warps
    __shared__ unsigned s_thr;
    __shared__ int s_cnt;
    __shared__ u64 s_pool[POOL_CAP];

    const int t = threadIdx.x;
    const int lane = t & 31;
    const int wid = t >> 5;
    const size_t row = blockIdx.x;
    const float4* rp = reinterpret_cast<const float4*>(in + row * (size_t)ROWLEN);

    // Front-batched streaming loads: 4x LDG.128 per thread.
    float4 v0 = __ldcs(rp + t);
    float4 v1 = __ldcs(rp + 256 + t);
    float4 v2 = __ldcs(rp + 512 + t);
    float4 v3 = __ldcs(rp + 768 + t);

    if (t == 0) s_cnt = 0;

    // Per-thread max over its 16 elements.
    float m01 = fmaxf(fmaxf(fmaxf(v0.x, v0.y), fmaxf(v0.z, v0.w)),
                      fmaxf(fmaxf(v1.x, v1.y), fmaxf(v1.z, v1.w)));
    float m23 = fmaxf(fmaxf(fmaxf(v2.x, v2.y), fmaxf(v2.z, v2.w)),
                      fmaxf(fmaxf(v3.x, v3.y), fmaxf(v3.z, v3.w)));
    const float gmax = fmaxf(m01, m23);
    const unsigned gx = fflip(gmax);

    // Warp top-2 (distinct) via two shuffle max-reductions.
    unsigned m1 = gx;
#pragma unroll
    for (int off = 16; off > 0; off >>= 1)
        m1 = max(m1, __shfl_xor_sync(0xffffffffu, m1, off));
    unsigned rest = (gx == m1) ? 0u : gx;     // zero out ALL holders of m1 (ties only loosen m2 -> safe)
    unsigned m2 = rest;
#pragma unroll
    for (int off = 16; off > 0; off >>= 1)
        m2 = max(m2, __shfl_xor_sync(0xffffffffu, m2, off));

    if (lane == 0) { s_m[wid * 2] = m1; s_m[wid * 2 + 1] = m2; }
    __syncthreads();

    // Warp 0: T = 8th largest of the 16 published values (zero-padded 32-lane
    // bitonic sort, ascending -> 8th largest at lane 24). Safety: each warp has
    // >=1 element >= m1_w and >=2 elements >= m2_w; summing guarantees over the
    // >=8 published values >= T yields >=8 distinct elements >= T.
    if (t < 32) {
        unsigned v = (lane < 16) ? s_m[lane] : 0u;
#pragma unroll
        for (int k = 2; k <= 32; k <<= 1) {
#pragma unroll
            for (int j = k >> 1; j > 0; j >>= 1) {
                unsigned o = __shfl_xor_sync(0xffffffffu, v, j);
                bool take_max = (((lane & j) != 0) ^ ((lane & k) != 0));
                v = take_max ? max(v, o) : min(v, o);
            }
        }
        if (lane == 24) s_thr = v;
    }
    __syncthreads();

    const float thr = funflip(s_thr);   // single LDS broadcast

    // Push candidate ELEMENTS (x >= thr). Typically ~10-14 per row.
    if (gmax >= thr) {
        const float4 vv[4] = {v0, v1, v2, v3};
#pragma unroll
        for (int c = 0; c < 4; c++) {
            const float* e = reinterpret_cast<const float*>(&vv[c]);
#pragma unroll
            for (int j = 0; j < 4; j++) {
                float x = e[j];
                if (x >= thr) {
                    int pos = atomicAdd(&s_cnt, 1);
                    if (pos < POOL_CAP) {
                        int idx = c * 1024 + 4 * t + j;
                        s_pool[pos] = ((u64)fflip(x) << 12) | (unsigned)(4095 - idx);
                    }
                }
            }
        }
    }
    __syncthreads();

    // Warp 0: select top-8 keys (value desc, index asc), write in index order.
    if (t < 32) {
        const int n = min(s_cnt, POOL_CAP);

        if (n <= 32) {
            // FAST PATH: one 32-lane bitonic sort of the zero-padded pool.
            u64 key = (t < n) ? s_pool[t] : 0ull;   // keys unique & nonzero
#pragma unroll
            for (int k = 2; k <= 32; k <<= 1) {
#pragma unroll
                for (int j = k >> 1; j > 0; j >>= 1) {
                    u64 o = __shfl_xor_sync(0xffffffffu, key, j);
                    bool take_max = (((lane & j) != 0) ^ ((lane & k) != 0));
                    key = take_max ? (key > o ? key : o) : (key < o ? key : o);
                }
            }
            // ascending: top-8 at lanes 24..31
            if (t >= 32 - KSEL) {
                unsigned fb = (unsigned)(key >> 12);
                float val = funflip(fb);
                int idx = 4095 - (int)(key & 0xfffu);
                int rank = 0;
#pragma unroll
                for (int j = 24; j < 32; j++) {
                    int oi = __shfl_sync(0xffffffffu, idx, j);
                    rank += (oi < idx);
                }
                out[row * KSEL + rank] = val;
            }
        } else {
            // SLOW PATH (rare): 8 rounds of warp-wide argmax.
            u64 mykey = 0ull;
#pragma unroll 1
            for (int k = 0; k < KSEL; k++) {
                u64 best = 0ull; int bpos = -1;
                for (int p = t; p < n; p += 32) {
                    u64 key = s_pool[p];
                    if (key > best) { best = key; bpos = p; }
                }
#pragma unroll
                for (int off = 16; off > 0; off >>= 1) {
                    u64 ob = __shfl_xor_sync(0xffffffffu, best, off);
                    int op = __shfl_xor_sync(0xffffffffu, bpos, off);
                    if (ob > best) { best = ob; bpos = op; }
                }
                if (t == k) mykey = best;
                if (t == 0) s_pool[bpos] = 0ull;
                __syncwarp();
            }
            if (t < KSEL) {
                unsigned fb = (unsigned)(mykey >> 12);
                float val = funflip(fb);
                int idx = 4095 - (int)(mykey & 0xfffu);
                int rank = 0;
#pragma unroll
                for (int j = 0; j < KSEL; j++) {
                    int oi = __shfl_sync(0xffu, idx, j);
                    rank += (oi < idx);
                }
                out[row * KSEL + rank] = val;
            }
        }
    }
}

extern "C" void kernel_launch(void* const* d_in, const int* in_sizes, int n_in,
                              void* d_out, int out_size) {
    const float* in = (const float*)d_in[0];
    float* out = (float*)d_out;
    int rows = in_sizes[0] / ROWLEN;   // B*C = 16384
    kmax_kernel<<<rows, NTHREADS>>>(in, out);
}

// round 5
// speedup vs baseline: 2.9410x; 1.0442x over previous
#include <cuda_runtime.h>
#include <cstdint>

#define NTHREADS 256
#define ROWLEN   4096
#define KSEL     8
#define POOL_CAP 256

typedef unsigned long long u64;

// Monotone bijection float -> uint32 (order preserving)
__device__ __forceinline__ unsigned fflip(float f) {
    unsigned u = __float_as_uint(f);
    return (u & 0x80000000u) ? ~u : (u | 0x80000000u);
}
__device__ __forceinline__ float funflip(unsigned u) {
    return __uint_as_float((u & 0x80000000u) ? (u ^ 0x80000000u) : ~u);
}

__device__ __forceinline__ void push_cand(float x, float thr, int idx,
                                          int* s_cnt, u64* s_pool) {
    if (x >= thr) {
        int pos = atomicAdd(s_cnt, 1);
        if (pos < POOL_CAP)
            s_pool[pos] = ((u64)fflip(x) << 12) | (unsigned)(4095 - idx);
    }
}

__global__ __launch_bounds__(NTHREADS) void kmax_kernel(const float* __restrict__ in,
                                                        float* __restrict__ out) {
    __shared__ unsigned s_m[16];      // per-warp {m1, m2} (flipped), 8 warps
    __shared__ unsigned s_thr;
    __shared__ int s_cnt;
    __shared__ u64 s_pool[POOL_CAP];

    const int t = threadIdx.x;
    const int lane = t & 31;
    const int wid = t >> 5;
    const size_t row = blockIdx.x;
    const float4* rp = reinterpret_cast<const float4*>(in + row * (size_t)ROWLEN);

    // Front-batched streaming loads: 4x LDG.128 per thread.
    float4 v0 = __ldcs(rp + t);
    float4 v1 = __ldcs(rp + 256 + t);
    float4 v2 = __ldcs(rp + 512 + t);
    float4 v3 = __ldcs(rp + 768 + t);

    if (t == 0) s_cnt = 0;

    // Per-thread max over its 16 elements (15 FMNMX).
    float m01 = fmaxf(fmaxf(fmaxf(v0.x, v0.y), fmaxf(v0.z, v0.w)),
                      fmaxf(fmaxf(v1.x, v1.y), fmaxf(v1.z, v1.w)));
    float m23 = fmaxf(fmaxf(fmaxf(v2.x, v2.y), fmaxf(v2.z, v2.w)),
                      fmaxf(fmaxf(v3.x, v3.y), fmaxf(v3.z, v3.w)));
    const float gmax = fmaxf(m01, m23);
    const unsigned gx = fflip(gmax);

    // Warp top-2 (distinct) via hardware REDUX (2 instructions instead of 2x
    // 5-step shuffle reductions). Ties zeroing all m1 holders only loosens m2
    // -> threshold stays safe.
    unsigned m1 = __reduce_max_sync(0xffffffffu, gx);
    unsigned m2 = __reduce_max_sync(0xffffffffu, (gx == m1) ? 0u : gx);

    if (lane == 0) { s_m[wid * 2] = m1; s_m[wid * 2 + 1] = m2; }
    __syncthreads();

    // Warp 0: T = 8th largest of the 16 published values (zero-padded 32-lane
    // bitonic, ascending -> 8th largest lands at lane 24). Safety: each warp
    // has >=1 element >= m1_w and >=2 elements >= m2_w; the >=8 published
    // values >= T therefore certify >=8 distinct elements >= T.
    if (t < 32) {
        unsigned v = (lane < 16) ? s_m[lane] : 0u;
#pragma unroll
        for (int k = 2; k <= 32; k <<= 1) {
#pragma unroll
            for (int j = k >> 1; j > 0; j >>= 1) {
                unsigned o = __shfl_xor_sync(0xffffffffu, v, j);
                bool take_max = (((lane & j) != 0) ^ ((lane & k) != 0));
                v = take_max ? max(v, o) : min(v, o);
            }
        }
        if (lane == 24) s_thr = v;
    }
    __syncthreads();

    const float thr = funflip(s_thr);   // single LDS broadcast

    // Push candidate ELEMENTS (x >= thr). Typically ~10-14 per row; the vast
    // majority of threads skip this branch entirely.
    if (gmax >= thr) {
        int i0 = 4 * t;
        push_cand(v0.x, thr, i0 + 0, &s_cnt, s_pool);
        push_cand(v0.y, thr, i0 + 1, &s_cnt, s_pool);
        push_cand(v0.z, thr, i0 + 2, &s_cnt, s_pool);
        push_cand(v0.w, thr, i0 + 3, &s_cnt, s_pool);
        push_cand(v1.x, thr, i0 + 1024, &s_cnt, s_pool);
        push_cand(v1.y, thr, i0 + 1025, &s_cnt, s_pool);
        push_cand(v1.z, thr, i0 + 1026, &s_cnt, s_pool);
        push_cand(v1.w, thr, i0 + 1027, &s_cnt, s_pool);
        push_cand(v2.x, thr, i0 + 2048, &s_cnt, s_pool);
        push_cand(v2.y, thr, i0 + 2049, &s_cnt, s_pool);
        push_cand(v2.z, thr, i0 + 2050, &s_cnt, s_pool);
        push_cand(v2.w, thr, i0 + 2051, &s_cnt, s_pool);
        push_cand(v3.x, thr, i0 + 3072, &s_cnt, s_pool);
        push_cand(v3.y, thr, i0 + 3073, &s_cnt, s_pool);
        push_cand(v3.z, thr, i0 + 3074, &s_cnt, s_pool);
        push_cand(v3.w, thr, i0 + 3075, &s_cnt, s_pool);
    }
    __syncthreads();

    // Warp 0: select top-8 keys (value desc, index asc), write in index order.
    if (t < 32) {
        const int n = min(s_cnt, POOL_CAP);

        if (n <= 32) {
            // FAST PATH: one 32-lane bitonic sort of the zero-padded pool.
            u64 key = (t < n) ? s_pool[t] : 0ull;   // keys unique & nonzero
#pragma unroll
            for (int k = 2; k <= 32; k <<= 1) {
#pragma unroll
                for (int j = k >> 1; j > 0; j >>= 1) {
                    u64 o = __shfl_xor_sync(0xffffffffu, key, j);
                    bool take_max = (((lane & j) != 0) ^ ((lane & k) != 0));
                    key = take_max ? (key > o ? key : o) : (key < o ? key : o);
                }
            }
            // ascending: top-8 at lanes 24..31
            if (t >= 32 - KSEL) {
                unsigned fb = (unsigned)(key >> 12);
                float val = funflip(fb);
                int idx = 4095 - (int)(key & 0xfffu);
                int rank = 0;
#pragma unroll
                for (int j = 24; j < 32; j++) {
                    int oi = __shfl_sync(0xffffffffu, idx, j);
                    rank += (oi < idx);
                }
                out[row * KSEL + rank] = val;
            }
        } else {
            // SLOW PATH (rare): 8 rounds of warp-wide argmax.
            u64 mykey = 0ull;
#pragma unroll 1
            for (int k = 0; k < KSEL; k++) {
                u64 best = 0ull; int bpos = -1;
                for (int p = t; p < n; p += 32) {
                    u64 key = s_pool[p];
                    if (key > best) { best = key; bpos = p; }
                }
#pragma unroll
                for (int off = 16; off > 0; off >>= 1) {
                    u64 ob = __shfl_xor_sync(0xffffffffu, best, off);
                    int op = __shfl_xor_sync(0xffffffffu, bpos, off);
                    if (ob > best) { best = ob; bpos = op; }
                }
                if (t == k) mykey = best;
                if (t == 0) s_pool[bpos] = 0ull;
                __syncwarp();
            }
            if (t < KSEL) {
                unsigned fb = (unsigned)(mykey >> 12);
                float val = funflip(fb);
                int idx = 4095 - (int)(mykey & 0xfffu);
                int rank = 0;
#pragma unroll
                for (int j = 0; j < KSEL; j++) {
                    int oi = __shfl_sync(0xffu, idx, j);
                    rank += (oi < idx);
                }
                out[row * KSEL + rank] = val;
            }
        }
    }
}

extern "C" void kernel_launch(void* const* d_in, const int* in_sizes, int n_in,
                              void* d_out, int out_size) {
    const float* in = (const float*)d_in[0];
    float* out = (float*)d_out;
    int rows = in_sizes[0] / ROWLEN;   // B*C = 16384
    kmax_kernel<<<rows, NTHREADS>>>(in, out);
}